// round 11
// baseline (speedup 1.0000x reference)
#include <cuda_runtime.h>
#include <cuda_fp16.h>
#include <cstdint>

#define BS_  8
#define N_   4096
#define B_   8
#define R_   64
#define D_   256

#define MTILE   64
#define THREADS 128
#define ROWB    272        // q/K/V smem row stride (128 fp16 data + 8 pad)
#define ROWW    144        // W smem row stride (64 fp16 data + 8 pad)

#define KV_ELEMS (BS_*B_*R_*D_)   // 1,048,576

// ---- smem layout (bytes) ----
#define SMO_A    0                      // q chunk fp16 [64][136] = 17408 (later V0)
#define SMO_B    17408                  // K chunk fp16 [64][136]         (later V1)
#define SMO_W    34816                  // W fp16 [64][72] = 9216
#define SMO_PART 44032                  // 128 floats: ssq partials [64][2]
#define SMO_INV  44544                  // 64 floats
#define SMEM_TOTAL 44800

// Pre-converted K and a*V (fp16), written by the prelude kernel.
__device__ __half g_Kf[KV_ELEMS];
__device__ __half g_Vf[KV_ELEMS];

__global__ __launch_bounds__(256)
void ProceduralMemory_81535659147884_cvt(const float* __restrict__ K,
                                         const float* __restrict__ V,
                                         const float* __restrict__ a)
{
    const int idx = blockIdx.x * 256 + threadIdx.x;      // per float2
    const float2 k2 = ((const float2*)K)[idx];
    const float2 v2 = ((const float2*)V)[idx];
    const float av = a[idx / (D_ / 2)];
    ((__half2*)g_Kf)[idx] = __floats2half2_rn(k2.x, k2.y);
    ((__half2*)g_Vf)[idx] = __floats2half2_rn(v2.x * av, v2.y * av);
}

__device__ __forceinline__ uint32_t smem_u32(const void* p) {
    uint32_t a;
    asm("{ .reg .u64 t; cvta.to.shared.u64 t, %1; cvt.u32.u64 %0, t; }" : "=r"(a) : "l"(p));
    return a;
}
__device__ __forceinline__ void cpa16(uint32_t dst, const void* src) {
    asm volatile("cp.async.cg.shared.global [%0], [%1], 16;" :: "r"(dst), "l"(src));
}
__device__ __forceinline__ void ldsm4(uint32_t* r, uint32_t addr) {
    asm volatile("ldmatrix.sync.aligned.m8n8.x4.shared.b16 {%0,%1,%2,%3}, [%4];"
                 : "=r"(r[0]), "=r"(r[1]), "=r"(r[2]), "=r"(r[3]) : "r"(addr));
}
__device__ __forceinline__ void ldsm4t(uint32_t* r, uint32_t addr) {
    asm volatile("ldmatrix.sync.aligned.m8n8.x4.trans.shared.b16 {%0,%1,%2,%3}, [%4];"
                 : "=r"(r[0]), "=r"(r[1]), "=r"(r[2]), "=r"(r[3]) : "r"(addr));
}
__device__ __forceinline__ void mma16816(float* c, const uint32_t* a, const uint32_t* b) {
    asm volatile("mma.sync.aligned.m16n8k16.row.col.f32.f16.f16.f32 "
                 "{%0,%1,%2,%3}, {%4,%5,%6,%7}, {%8,%9}, {%0,%1,%2,%3};"
                 : "+f"(c[0]), "+f"(c[1]), "+f"(c[2]), "+f"(c[3])
                 : "r"(a[0]), "r"(a[1]), "r"(a[2]), "r"(a[3]), "r"(b[0]), "r"(b[1]));
}
__device__ __forceinline__ uint32_t packh2(float x, float y) {
    __half2 h = __floats2half2_rn(x, y);
    return *(uint32_t*)&h;
}
__device__ __forceinline__ void cvt4h(float4 v, uint2& hi) {
    __half hx = __float2half_rn(v.x), hy = __float2half_rn(v.y);
    __half hz = __float2half_rn(v.z), hw = __float2half_rn(v.w);
    hi.x = (uint32_t)__half_as_ushort(hx) | ((uint32_t)__half_as_ushort(hy) << 16);
    hi.y = (uint32_t)__half_as_ushort(hz) | ((uint32_t)__half_as_ushort(hw) << 16);
}

__global__ __launch_bounds__(THREADS, 5)
void ProceduralMemory_81535659147884_kernel(
    const float* __restrict__ q,
    float* __restrict__ out)
{
    extern __shared__ char smc[];
    const uint32_t smb = smem_u32(smc);

    const int tid  = threadIdx.x;
    const int wid  = tid >> 5;        // 0..3
    const int lane = tid & 31;

    const int pair = blockIdx.x >> 6;          // 0..63
    const int tile = blockIdx.x & 63;          // 0..63
    const int s = pair >> 3, b = pair & 7;
    const int n0 = tile * MTILE;

    float* partS = (float*)(smc + SMO_PART);
    float* invS  = (float*)(smc + SMO_INV);

    // ================= GEMM1: 2x2 warp grid, warp tile 32 rows x 32 cols =================
    const int wm = wid & 1;           // row group (rows 32*wm ..)
    const int wn = wid >> 1;          // col group (cols 32*wn ..)

    float acc[2][4][4];               // [mtile][ntile][frag]
    #pragma unroll
    for (int mt = 0; mt < 2; ++mt)
        #pragma unroll
        for (int nt = 0; nt < 4; ++nt)
            #pragma unroll
            for (int i = 0; i < 4; ++i) acc[mt][nt][i] = 0.f;

    const uint32_t aOff = (uint32_t)(32 * wm + (lane & 15)) * ROWB +
                          (uint32_t)(lane >> 4) * 16u;
    const uint32_t bOff = (uint32_t)(32 * wn + (lane & 7) + ((lane & 16) >> 1)) * ROWB +
                          (uint32_t)((lane >> 3) & 1) * 16u;

    #pragma unroll 1
    for (int c = 0; c < 2; ++c) {
        if (c > 0) __syncthreads();   // GEMM1 chunk0 done reading buffers

        // ---- Issue K chunk cp.async first (flies under the q work below) ----
        {
            const __half* ks = g_Kf + (size_t)pair * (R_ * D_) + c * 128;
            #pragma unroll
            for (int g = 0; g < 8; ++g) {
                const int idx = g * 128 + tid;        // 0..1023
                const int r = idx >> 4, gc = idx & 15;
                cpa16(smb + SMO_B + (uint32_t)r * ROWB + (uint32_t)gc * 16u,
                      ks + (size_t)r * D_ + gc * 8);
            }
            asm volatile("cp.async.commit_group;" ::: "memory");
        }

        // ---- Load q chunk [64 rows, cols 128c..], cvt fp16, ssq partials ----
        {
            const float4* qg = (const float4*)q;
            #pragma unroll 4
            for (int rr = 0; rr < 16; ++rr) {
                const int m = 16 * wid + rr;
                float4 v = qg[((size_t)(s * N_ + n0 + m) * B_ + b) * 64 + c * 32 + lane];
                float ss = v.x * v.x + v.y * v.y + v.z * v.z + v.w * v.w;
                #pragma unroll
                for (int o = 16; o; o >>= 1) ss += __shfl_xor_sync(0xFFFFFFFFu, ss, o);
                if (lane == 0) partS[m * 2 + c] = ss;
                uint2 hi; cvt4h(v, hi);
                *(uint2*)(smc + SMO_A + (uint32_t)m * ROWB + (uint32_t)lane * 8u) = hi;
            }
        }
        asm volatile("cp.async.wait_group 0;" ::: "memory");
        __syncthreads();

        if (c == 1 && tid < MTILE)
            invS[tid] = 1.0f / fmaxf(sqrtf(partS[2 * tid] + partS[2 * tid + 1]), 1e-8f);

        // ---- GEMM1 partial: 2 A-ldsm + 2 B-ldsm + 8 mma per k-step ----
        #pragma unroll
        for (int k = 0; k < 8; ++k) {
            uint32_t a0[4], a1[4], b0[4], b1[4];
            ldsm4(a0, smb + SMO_A + aOff + (uint32_t)k * 32u);
            ldsm4(a1, smb + SMO_A + aOff + 16u * ROWB + (uint32_t)k * 32u);
            ldsm4(b0, smb + SMO_B + bOff + (uint32_t)k * 32u);
            ldsm4(b1, smb + SMO_B + bOff + 16u * ROWB + (uint32_t)k * 32u);
            mma16816(acc[0][0], a0, b0 + 0);
            mma16816(acc[0][1], a0, b0 + 2);
            mma16816(acc[0][2], a0, b1 + 0);
            mma16816(acc[0][3], a0, b1 + 2);
            mma16816(acc[1][0], a1, b0 + 0);
            mma16816(acc[1][1], a1, b0 + 2);
            mma16816(acc[1][2], a1, b1 + 0);
            mma16816(acc[1][3], a1, b1 + 2);
        }
    }
    __syncthreads();   // GEMM1 done reading A/B buffers; invS visible below

    // ---- Issue BOTH V chunks now (single commit group): V0 -> A, V1 -> B ----
    {
        const __half* vs = g_Vf + (size_t)pair * (R_ * D_);
        #pragma unroll
        for (int g = 0; g < 8; ++g) {
            const int idx = g * 128 + tid;
            const int r = idx >> 4, gc = idx & 15;
            cpa16(smb + SMO_A + (uint32_t)r * ROWB + (uint32_t)gc * 16u,
                  vs + (size_t)r * D_ + gc * 8);
            cpa16(smb + SMO_B + (uint32_t)r * ROWB + (uint32_t)gc * 16u,
                  vs + (size_t)r * D_ + 128 + gc * 8);
        }
        asm volatile("cp.async.commit_group;" ::: "memory");
    }

    // ---- Epilogue1 (overlaps V copies): w = score * inv -> fp16 W in smem ----
    {
        #pragma unroll
        for (int mt = 0; mt < 2; ++mt) {
            const int r0 = 32 * wm + 16 * mt + (lane >> 2);
            const float inv0 = invS[r0], inv1 = invS[r0 + 8];
            #pragma unroll
            for (int nt = 0; nt < 4; ++nt) {
                const int col = 32 * wn + 8 * nt + 2 * (lane & 3);
                *(uint32_t*)(smc + SMO_W + (uint32_t)r0 * ROWW + (uint32_t)col * 2u) =
                    packh2(acc[mt][nt][0] * inv0, acc[mt][nt][1] * inv0);
                *(uint32_t*)(smc + SMO_W + (uint32_t)(r0 + 8) * ROWW + (uint32_t)col * 2u) =
                    packh2(acc[mt][nt][2] * inv1, acc[mt][nt][3] * inv1);
            }
        }
    }
    asm volatile("cp.async.wait_group 0;" ::: "memory");
    __syncthreads();   // W visible + V0/V1 visible

    // ============ GEMM2: warp tile 64 rows x 64 cols; A from smem W ============
    // warp wid owns output cols [64*wid, 64*wid+64): buffer = wid>>1, half = wid&1
    const uint32_t vBase = smb + ((wid >> 1) ? SMO_B : SMO_A) + (uint32_t)(wid & 1) * 128u +
                           (uint32_t)(lane & 15) * ROWB + (uint32_t)(lane >> 4) * 16u;
    const uint32_t wOff  = smb + SMO_W + (uint32_t)(lane & 15) * ROWW +
                           (uint32_t)(lane >> 4) * 16u;
    const int colg = 64 * wid + 2 * (lane & 3);

    #pragma unroll 1
    for (int msub = 0; msub < 2; ++msub) {      // rows 32*msub .. +32
        float acc2[2][4][4];                    // [mtile][bb-group][frag pair x2]
        float acc3[2][4][4];                    // second ntile of each bb-group
        #pragma unroll
        for (int mt = 0; mt < 2; ++mt)
            #pragma unroll
            for (int g = 0; g < 4; ++g)
                #pragma unroll
                for (int i = 0; i < 4; ++i) { acc2[mt][g][i] = 0.f; acc3[mt][g][i] = 0.f; }

        #pragma unroll
        for (int k = 0; k < 4; ++k) {
            uint32_t af0[4], af1[4];
            ldsm4(af0, wOff + (uint32_t)(32 * msub) * ROWW + (uint32_t)k * 32u);
            ldsm4(af1, wOff + (uint32_t)(32 * msub + 16) * ROWW + (uint32_t)k * 32u);
            #pragma unroll
            for (int g = 0; g < 4; ++g) {
                uint32_t bb[4];
                ldsm4t(bb, vBase + (uint32_t)k * (16u * ROWB) + (uint32_t)g * 32u);
                mma16816(acc2[0][g], af0, bb + 0);
                mma16816(acc3[0][g], af0, bb + 2);
                mma16816(acc2[1][g], af1, bb + 0);
                mma16816(acc3[1][g], af1, bb + 2);
            }
        }

        // ---- Epilogue2: out = q * mod (q re-read from gmem, L2-resident) ----
        #pragma unroll
        for (int mt = 0; mt < 2; ++mt) {
            #pragma unroll
            for (int h = 0; h < 2; ++h) {
                const int m = 32 * msub + 16 * mt + (lane >> 2) + 8 * h;
                const size_t gbase = ((size_t)(s * N_ + n0 + m) * B_ + b) * D_;
                #pragma unroll
                for (int g = 0; g < 4; ++g) {
                    {
                        const int col = colg + 16 * g;
                        float2 qv = *(const float2*)(q + gbase + col);
                        float2 o;
                        o.x = qv.x * acc2[mt][g][2 * h];
                        o.y = qv.y * acc2[mt][g][2 * h + 1];
                        *(float2*)(out + gbase + col) = o;
                    }
                    {
                        const int col = colg + 16 * g + 8;
                        float2 qv = *(const float2*)(q + gbase + col);
                        float2 o;
                        o.x = qv.x * acc3[mt][g][2 * h];
                        o.y = qv.y * acc3[mt][g][2 * h + 1];
                        *(float2*)(out + gbase + col) = o;
                    }
                }
            }
        }
    }
}

extern "C" void kernel_launch(void* const* d_in, const int* in_sizes, int n_in,
                              void* d_out, int out_size)
{
    const float* q    = (const float*)d_in[0];
    const float* pm_K = (const float*)d_in[1];
    const float* pm_V = (const float*)d_in[2];
    const float* pm_a = (const float*)d_in[3];
    float* out = (float*)d_out;

    cudaFuncSetAttribute(ProceduralMemory_81535659147884_kernel,
                         cudaFuncAttributeMaxDynamicSharedMemorySize, SMEM_TOTAL);

    // Prelude: convert K -> fp16, a*V -> fp16 into device scratch (~2us)
    ProceduralMemory_81535659147884_cvt<<<KV_ELEMS / 512, 256>>>(pm_K, pm_V, pm_a);

    dim3 grid(BS_ * B_ * (N_ / MTILE));   // 4096 CTAs
    ProceduralMemory_81535659147884_kernel<<<grid, THREADS, SMEM_TOTAL>>>(q, out);
}